// round 4
// baseline (speedup 1.0000x reference)
#include <cuda_runtime.h>
#include <cuda_bf16.h>
#include <mma.h>
#include <cstdint>

using namespace nvcuda;

#define NN 50000
#define NP 50048          // padded to multiple of 128
#define NE 800000
#define ET 850000         // NE + NN self loops
#define NS 0.2f

// ---------------- scratch (device globals) -----------------------------------
__device__ float g_h1[NP * 128];
__device__ float g_out1[NN * 128];
__device__ float g_as1[NN * 4];
__device__ float g_ad1[NN * 4];
__device__ float g_h2[NP * 64];
__device__ float g_as2[NN];
__device__ float g_ad2[NN];
__device__ int g_deg[NN];
__device__ int g_off[NN + 1];
__device__ int g_cur[NN];
__device__ int g_srcidx[ET];
// bf16-split weights
__device__ __nv_bfloat16 g_w1h[128 * 128];
__device__ __nv_bfloat16 g_w1l[128 * 128];
__device__ __nv_bfloat16 g_w2h[128 * 64];
__device__ __nv_bfloat16 g_w2l[128 * 64];

__device__ __forceinline__ float lrelu(float v) { return v >= 0.f ? v : NS * v; }

// ---------------- weight conversion (bf16 hi/lo split) ------------------------
__global__ void k_convw(const float* __restrict__ W1, const float* __restrict__ W2) {
    int t = blockIdx.x * blockDim.x + threadIdx.x;
    if (t < 128 * 128) {
        float w = W1[t];
        __nv_bfloat16 h = __float2bfloat16(w);
        g_w1h[t] = h;
        g_w1l[t] = __float2bfloat16(w - __bfloat162float(h));
    }
    if (t < 128 * 64) {
        float w = W2[t];
        __nv_bfloat16 h = __float2bfloat16(w);
        g_w2h[t] = h;
        g_w2l[t] = __float2bfloat16(w - __bfloat162float(h));
    }
}

// ---------------- GEMM1: h1 = x @ W1 (wmma bf16 split) ------------------------
// block 256 threads (8 warps), M-tile 128, N=128; warp tile 32x64
#define LDA 136
__global__ __launch_bounds__(256)
void k_gemm1_mma(const float* __restrict__ X) {
    __shared__ __nv_bfloat16 sAh[128 * LDA];
    __shared__ __nv_bfloat16 sAl[128 * LDA];
    int row0 = blockIdx.x * 128;

    // load + split X tile into smem
    for (int i = threadIdx.x; i < 4096; i += 256) {      // 4096 float4 = 128x128
        int r = i >> 5, c4 = i & 31;
        float4 v = make_float4(0.f, 0.f, 0.f, 0.f);
        if (row0 + r < NN) v = ((const float4*)X)[(size_t)(row0 + r) * 32 + c4];
        int base = r * LDA + c4 * 4;
        float vv[4] = {v.x, v.y, v.z, v.w};
#pragma unroll
        for (int j = 0; j < 4; j++) {
            __nv_bfloat16 h = __float2bfloat16(vv[j]);
            sAh[base + j] = h;
            sAl[base + j] = __float2bfloat16(vv[j] - __bfloat162float(h));
        }
    }
    __syncthreads();

    int w = threadIdx.x >> 5;
    int wr = w >> 1, wc = w & 1;

    wmma::fragment<wmma::accumulator, 16, 16, 16, float> c[2][4];
#pragma unroll
    for (int i = 0; i < 2; i++)
#pragma unroll
        for (int j = 0; j < 4; j++) wmma::fill_fragment(c[i][j], 0.f);

    for (int kk = 0; kk < 128; kk += 16) {
        wmma::fragment<wmma::matrix_a, 16, 16, 16, __nv_bfloat16, wmma::row_major> ah[2], al[2];
#pragma unroll
        for (int i = 0; i < 2; i++) {
            wmma::load_matrix_sync(ah[i], sAh + (wr * 32 + i * 16) * LDA + kk, LDA);
            wmma::load_matrix_sync(al[i], sAl + (wr * 32 + i * 16) * LDA + kk, LDA);
        }
#pragma unroll
        for (int j = 0; j < 4; j++) {
            wmma::fragment<wmma::matrix_b, 16, 16, 16, __nv_bfloat16, wmma::row_major> bh, bl;
            wmma::load_matrix_sync(bh, g_w1h + kk * 128 + wc * 64 + j * 16, 128);
            wmma::load_matrix_sync(bl, g_w1l + kk * 128 + wc * 64 + j * 16, 128);
#pragma unroll
            for (int i = 0; i < 2; i++) {
                wmma::mma_sync(c[i][j], ah[i], bh, c[i][j]);
                wmma::mma_sync(c[i][j], al[i], bh, c[i][j]);
                wmma::mma_sync(c[i][j], ah[i], bl, c[i][j]);
            }
        }
    }
#pragma unroll
    for (int i = 0; i < 2; i++)
#pragma unroll
        for (int j = 0; j < 4; j++)
            wmma::store_matrix_sync(
                g_h1 + (size_t)(row0 + wr * 32 + i * 16) * 128 + wc * 64 + j * 16,
                c[i][j], 128, wmma::mem_row_major);
}

// ---------------- GEMM2: h2 = relu(out1) @ W2 (wmma bf16 split) ---------------
// block 256 threads (8 warps), M-tile 128, N=64; warp tile 32x32
__global__ __launch_bounds__(256)
void k_gemm2_mma() {
    __shared__ __nv_bfloat16 sAh[128 * LDA];
    __shared__ __nv_bfloat16 sAl[128 * LDA];
    int row0 = blockIdx.x * 128;

    for (int i = threadIdx.x; i < 4096; i += 256) {
        int r = i >> 5, c4 = i & 31;
        float4 v = make_float4(0.f, 0.f, 0.f, 0.f);
        if (row0 + r < NN) v = ((const float4*)g_out1)[(size_t)(row0 + r) * 32 + c4];
        int base = r * LDA + c4 * 4;
        float vv[4] = {fmaxf(v.x, 0.f), fmaxf(v.y, 0.f), fmaxf(v.z, 0.f), fmaxf(v.w, 0.f)};
#pragma unroll
        for (int j = 0; j < 4; j++) {
            __nv_bfloat16 h = __float2bfloat16(vv[j]);
            sAh[base + j] = h;
            sAl[base + j] = __float2bfloat16(vv[j] - __bfloat162float(h));
        }
    }
    __syncthreads();

    int w = threadIdx.x >> 5;
    int wr = w >> 1, wc = w & 1;

    wmma::fragment<wmma::accumulator, 16, 16, 16, float> c[2][2];
#pragma unroll
    for (int i = 0; i < 2; i++)
#pragma unroll
        for (int j = 0; j < 2; j++) wmma::fill_fragment(c[i][j], 0.f);

    for (int kk = 0; kk < 128; kk += 16) {
        wmma::fragment<wmma::matrix_a, 16, 16, 16, __nv_bfloat16, wmma::row_major> ah[2], al[2];
#pragma unroll
        for (int i = 0; i < 2; i++) {
            wmma::load_matrix_sync(ah[i], sAh + (wr * 32 + i * 16) * LDA + kk, LDA);
            wmma::load_matrix_sync(al[i], sAl + (wr * 32 + i * 16) * LDA + kk, LDA);
        }
#pragma unroll
        for (int j = 0; j < 2; j++) {
            wmma::fragment<wmma::matrix_b, 16, 16, 16, __nv_bfloat16, wmma::row_major> bh, bl;
            wmma::load_matrix_sync(bh, g_w2h + kk * 64 + wc * 32 + j * 16, 64);
            wmma::load_matrix_sync(bl, g_w2l + kk * 64 + wc * 32 + j * 16, 64);
#pragma unroll
            for (int i = 0; i < 2; i++) {
                wmma::mma_sync(c[i][j], ah[i], bh, c[i][j]);
                wmma::mma_sync(c[i][j], al[i], bh, c[i][j]);
                wmma::mma_sync(c[i][j], ah[i], bl, c[i][j]);
            }
        }
    }
#pragma unroll
    for (int i = 0; i < 2; i++)
#pragma unroll
        for (int j = 0; j < 2; j++)
            wmma::store_matrix_sync(
                g_h2 + (size_t)(row0 + wr * 32 + i * 16) * 64 + wc * 32 + j * 16,
                c[i][j], 64, wmma::mem_row_major);
}

// ---------------- alpha kernels -----------------------------------------------
__global__ void k_alpha1(const float* __restrict__ asr, const float* __restrict__ adt) {
    int n = blockIdx.x * 4 + (threadIdx.x >> 5);
    if (n >= NN) return;
    int lane = threadIdx.x & 31;
    float4 h = *(const float4*)(g_h1 + (size_t)n * 128 + 4 * lane);
    float4 s = *(const float4*)(asr + 4 * lane);
    float4 d = *(const float4*)(adt + 4 * lane);
    float ps = h.x * s.x + h.y * s.y + h.z * s.z + h.w * s.w;
    float pd = h.x * d.x + h.y * d.y + h.z * d.z + h.w * d.w;
#pragma unroll
    for (int o = 4; o >= 1; o >>= 1) {
        ps += __shfl_down_sync(0xffffffffu, ps, o, 8);
        pd += __shfl_down_sync(0xffffffffu, pd, o, 8);
    }
    if ((lane & 7) == 0) {
        g_as1[n * 4 + (lane >> 3)] = ps;
        g_ad1[n * 4 + (lane >> 3)] = pd;
    }
}

__global__ void k_alpha2(const float* __restrict__ asr, const float* __restrict__ adt) {
    int n = blockIdx.x * 8 + (threadIdx.x >> 5);
    if (n >= NN) return;
    int lane = threadIdx.x & 31;
    float2 h = *(const float2*)(g_h2 + (size_t)n * 64 + 2 * lane);
    float2 s = *(const float2*)(asr + 2 * lane);
    float2 d = *(const float2*)(adt + 2 * lane);
    float ps = h.x * s.x + h.y * s.y;
    float pd = h.x * d.x + h.y * d.y;
#pragma unroll
    for (int o = 16; o >= 1; o >>= 1) {
        ps += __shfl_xor_sync(0xffffffffu, ps, o);
        pd += __shfl_xor_sync(0xffffffffu, pd, o);
    }
    if (lane == 0) { g_as2[n] = ps; g_ad2[n] = pd; }
}

// ---------------- CSR construction ------------------------------------------
__device__ __forceinline__ void edge_sd(int e, const int* __restrict__ ei, int& s, int& d) {
    if (e < NE) { s = ei[e]; d = ei[NE + e]; }
    else        { s = e - NE; d = s; }
}

__global__ void k_deginit() {
    int i = blockIdx.x * blockDim.x + threadIdx.x;
    if (i < NN) g_deg[i] = 1;
}

__global__ void k_hist(const int* __restrict__ ei) {
    int e = blockIdx.x * blockDim.x + threadIdx.x;
    if (e >= NE) return;
    atomicAdd(&g_deg[ei[NE + e]], 1);
}

__global__ void k_scan() {
    __shared__ int sh[1024];
    int carry = 0;
    for (int base = 0; base < NN; base += 4096) {
        int idx = base + threadIdx.x * 4;
        int v0 = (idx + 0 < NN) ? g_deg[idx + 0] : 0;
        int v1 = (idx + 1 < NN) ? g_deg[idx + 1] : 0;
        int v2 = (idx + 2 < NN) ? g_deg[idx + 2] : 0;
        int v3 = (idx + 3 < NN) ? g_deg[idx + 3] : 0;
        int ts = v0 + v1 + v2 + v3;
        sh[threadIdx.x] = ts;
        __syncthreads();
        for (int o = 1; o < 1024; o <<= 1) {
            int t = (threadIdx.x >= o) ? sh[threadIdx.x - o] : 0;
            __syncthreads();
            sh[threadIdx.x] += t;
            __syncthreads();
        }
        int excl = carry + sh[threadIdx.x] - ts;
        if (idx + 0 < NN) { g_off[idx + 0] = excl;                 g_cur[idx + 0] = excl; }
        if (idx + 1 < NN) { g_off[idx + 1] = excl + v0;            g_cur[idx + 1] = excl + v0; }
        if (idx + 2 < NN) { g_off[idx + 2] = excl + v0 + v1;       g_cur[idx + 2] = excl + v0 + v1; }
        if (idx + 3 < NN) { g_off[idx + 3] = excl + v0 + v1 + v2;  g_cur[idx + 3] = excl + v0 + v1 + v2; }
        carry += sh[1023];
        __syncthreads();
    }
    if (threadIdx.x == 0) g_off[NN] = carry;
}

__global__ void k_fill(const int* __restrict__ ei) {
    int e = blockIdx.x * blockDim.x + threadIdx.x;
    if (e >= ET) return;
    int s, d; edge_sd(e, ei, s, d);
    int pos = atomicAdd(&g_cur[d], 1);
    g_srcidx[pos] = s;
}

// ---------------- gather1: fused online-softmax aggregation (4 heads) --------
__global__ void k_gather1(const float* __restrict__ b1) {
    int n = blockIdx.x * 8 + (threadIdx.x >> 5);
    if (n >= NN) return;
    int lane = threadIdx.x & 31, h = lane >> 3;
    float adh = g_ad1[4 * n + h];
    int beg = g_off[n], end = g_off[n + 1];

    float m = -3.4e38f, den = 0.f;
    float4 acc = make_float4(0.f, 0.f, 0.f, 0.f);

    int s0 = 0; float a0 = 0.f; float4 hv0 = make_float4(0.f, 0.f, 0.f, 0.f);
    if (beg < end) {
        s0 = g_srcidx[beg];
        a0 = g_as1[4 * s0 + h];
        hv0 = *(const float4*)(g_h1 + (size_t)s0 * 128 + 4 * lane);
    }
    for (int j = beg; j < end; j++) {
        int s1 = 0; float a1 = 0.f; float4 hv1 = make_float4(0.f, 0.f, 0.f, 0.f);
        if (j + 1 < end) {
            s1 = g_srcidx[j + 1];
            a1 = g_as1[4 * s1 + h];
            hv1 = *(const float4*)(g_h1 + (size_t)s1 * 128 + 4 * lane);
        }
        float e = lrelu(a0 + adh);
        float nm = fmaxf(m, e);
        float sc = __expf(m - nm);
        float w = __expf(e - nm);
        den = den * sc + w;
        acc.x = acc.x * sc + w * hv0.x;
        acc.y = acc.y * sc + w * hv0.y;
        acc.z = acc.z * sc + w * hv0.z;
        acc.w = acc.w * sc + w * hv0.w;
        m = nm;
        s0 = s1; a0 = a1; hv0 = hv1;
    }
    float inv = 1.f / (den + 1e-16f);
    float4 bv = *(const float4*)(b1 + 4 * lane);
    *(float4*)(g_out1 + (size_t)n * 128 + 4 * lane) =
        make_float4(acc.x * inv + bv.x, acc.y * inv + bv.y,
                    acc.z * inv + bv.z, acc.w * inv + bv.w);
}

// ---------------- gather2 -----------------------------------------------------
__global__ void k_gather2(const float* __restrict__ b2, float* __restrict__ out) {
    int n = blockIdx.x * 8 + (threadIdx.x >> 5);
    if (n >= NN) return;
    int lane = threadIdx.x & 31;
    float adh = g_ad2[n];
    int beg = g_off[n], end = g_off[n + 1];

    float m = -3.4e38f, den = 0.f;
    float2 acc = make_float2(0.f, 0.f);

    int s0 = 0; float a0 = 0.f; float2 hv0 = make_float2(0.f, 0.f);
    if (beg < end) {
        s0 = g_srcidx[beg];
        a0 = g_as2[s0];
        hv0 = *(const float2*)(g_h2 + (size_t)s0 * 64 + 2 * lane);
    }
    for (int j = beg; j < end; j++) {
        int s1 = 0; float a1 = 0.f; float2 hv1 = make_float2(0.f, 0.f);
        if (j + 1 < end) {
            s1 = g_srcidx[j + 1];
            a1 = g_as2[s1];
            hv1 = *(const float2*)(g_h2 + (size_t)s1 * 64 + 2 * lane);
        }
        float e = lrelu(a0 + adh);
        float nm = fmaxf(m, e);
        float sc = __expf(m - nm);
        float w = __expf(e - nm);
        den = den * sc + w;
        acc.x = acc.x * sc + w * hv0.x;
        acc.y = acc.y * sc + w * hv0.y;
        m = nm;
        s0 = s1; a0 = a1; hv0 = hv1;
    }
    float inv = 1.f / (den + 1e-16f);
    float2 bv = *(const float2*)(b2 + 2 * lane);
    *(float2*)(out + (size_t)n * 64 + 2 * lane) =
        make_float2(acc.x * inv + bv.x, acc.y * inv + bv.y);
}

// ---------------- launch ------------------------------------------------------
extern "C" void kernel_launch(void* const* d_in, const int* in_sizes, int n_in,
                              void* d_out, int out_size) {
    const float* x   = (const float*)d_in[0];
    const int*   ei  = (const int*)d_in[1];
    const float* W1  = (const float*)d_in[2];
    const float* as1 = (const float*)d_in[3];
    const float* ad1 = (const float*)d_in[4];
    const float* b1  = (const float*)d_in[5];
    const float* W2  = (const float*)d_in[6];
    const float* as2 = (const float*)d_in[7];
    const float* ad2 = (const float*)d_in[8];
    const float* b2  = (const float*)d_in[9];
    float* out = (float*)d_out;

    // CSR build
    k_deginit<<<(NN + 255) / 256, 256>>>();
    k_hist<<<(NE + 255) / 256, 256>>>(ei);
    k_scan<<<1, 1024>>>();
    k_fill<<<(ET + 255) / 256, 256>>>(ei);

    // weights -> bf16 split
    k_convw<<<64, 256>>>(W1, W2);

    // layer 1
    k_gemm1_mma<<<NP / 128, 256>>>(x);
    k_alpha1<<<(NN + 3) / 4, 128>>>(as1, ad1);
    k_gather1<<<(NN + 7) / 8, 256>>>(b1);

    // layer 2
    k_gemm2_mma<<<NP / 128, 256>>>();
    k_alpha2<<<(NN + 7) / 8, 256>>>(as2, ad2);
    k_gather2<<<(NN + 7) / 8, 256>>>(b2, out);
}

// round 5
// speedup vs baseline: 1.1276x; 1.1276x over previous
#include <cuda_runtime.h>
#include <cuda_bf16.h>
#include <cuda_fp16.h>
#include <mma.h>
#include <cstdint>

using namespace nvcuda;

#define NN 50000
#define NP 50048          // 391 * 128
#define NE 800000
#define ET 850000         // NE + NN self loops
#define NS 0.2f
#define NBLK 196          // ceil(NN/256)

// ---------------- scratch (device globals) -----------------------------------
__device__ __half g_h1h[NN * 128];
__device__ float  g_out1[NN * 128];
__device__ float  g_as1[NN * 4];
__device__ float  g_ad1[NN * 4];
__device__ __half g_h2h[NN * 64];
__device__ float  g_as2[NN];
__device__ float  g_ad2[NN];
__device__ int g_deg[NN];
__device__ int g_off[NN + 1];
__device__ int g_cur[NN];
__device__ int g_srcidx[ET];
__device__ int g_bsum[NBLK];
__device__ int g_boff[NBLK];
// bf16-split weights with fused alpha columns
__device__ __nv_bfloat16 g_w1h[128 * 144];   // cols 0..127 W1, 128..135 W1@P, 136..143 zero
__device__ __nv_bfloat16 g_w1l[128 * 144];
__device__ __nv_bfloat16 g_w2h[128 * 80];    // cols 0..63 W2, 64..65 W2@P2, 66..79 zero
__device__ __nv_bfloat16 g_w2l[128 * 80];

__device__ __forceinline__ float lrelu(float v) { return v >= 0.f ? v : NS * v; }

// ---------------- weight conversion + fused alpha columns ---------------------
__global__ void k_convw(const float* __restrict__ W1, const float* __restrict__ W2,
                        const float* __restrict__ as1, const float* __restrict__ ad1,
                        const float* __restrict__ as2, const float* __restrict__ ad2) {
    int s = blockIdx.x * blockDim.x + threadIdx.x;
    float val; int dsth = -1, dstl = -1;
    if (s < 16384) {                       // W1 copy
        int k = s >> 7, n = s & 127;
        val = W1[k * 128 + n];
        dsth = k * 144 + n; dstl = 1;
    } else if (s < 17408) {                // W1 @ P (alpha cols)
        int i = s - 16384;
        int k = i >> 3, c = i & 7, h = c >> 1, isd = c & 1;
        const float* a = isd ? ad1 : as1;
        float sum = 0.f;
#pragma unroll
        for (int f = 0; f < 32; f++) sum += W1[k * 128 + h * 32 + f] * a[h * 32 + f];
        val = sum; dsth = k * 144 + 128 + c; dstl = 1;
    } else if (s < 18432) {                // W1 zero pad
        int i = s - 17408;
        int k = i >> 3, c = i & 7;
        val = 0.f; dsth = k * 144 + 136 + c; dstl = 1;
    } else if (s < 26624) {                // W2 copy
        int i = s - 18432;
        int k = i >> 6, n = i & 63;
        val = W2[k * 64 + n];
        dsth = k * 80 + n; dstl = 2;
    } else if (s < 26880) {                // W2 @ P2
        int i = s - 26624;
        int k = i >> 1, c = i & 1;
        const float* a = c ? ad2 : as2;
        float sum = 0.f;
#pragma unroll
        for (int f = 0; f < 64; f++) sum += W2[k * 64 + f] * a[f];
        val = sum; dsth = k * 80 + 64 + c; dstl = 2;
    } else if (s < 28672) {                // W2 zero pad
        int i = s - 26880;
        int k = i / 14, c = i % 14;
        val = 0.f; dsth = k * 80 + 66 + c; dstl = 2;
    } else return;
    __nv_bfloat16 hi = __float2bfloat16(val);
    __nv_bfloat16 lo = __float2bfloat16(val - __bfloat162float(hi));
    if (dstl == 1) { g_w1h[dsth] = hi; g_w1l[dsth] = lo; }
    else           { g_w2h[dsth] = hi; g_w2l[dsth] = lo; }
}

// ---------------- GEMM1: [h1 | as1 | ad1] = x @ [W1 | W1@P] -------------------
// 256 thr (8 warps), M-tile 128, N=144; warp = 16 rows x 144 cols (9 frags)
#define LDA 136
#define ST1 148
__global__ __launch_bounds__(256)
void k_gemm1_mma(const float* __restrict__ X) {
    extern __shared__ char raw[];
    __nv_bfloat16* sAh = (__nv_bfloat16*)raw;
    __nv_bfloat16* sAl = sAh + 128 * LDA;
    float* stage = (float*)raw;
    int tid = threadIdx.x;
    int row0 = blockIdx.x * 128;

    for (int i = tid; i < 4096; i += 256) {
        int r = i >> 5, c4 = i & 31;
        float4 v = make_float4(0.f, 0.f, 0.f, 0.f);
        if (row0 + r < NN) v = ((const float4*)X)[(size_t)(row0 + r) * 32 + c4];
        int base = r * LDA + c4 * 4;
        float vv[4] = {v.x, v.y, v.z, v.w};
#pragma unroll
        for (int j = 0; j < 4; j++) {
            __nv_bfloat16 h = __float2bfloat16(vv[j]);
            sAh[base + j] = h;
            sAl[base + j] = __float2bfloat16(vv[j] - __bfloat162float(h));
        }
    }
    __syncthreads();

    int w = tid >> 5;
    wmma::fragment<wmma::accumulator, 16, 16, 16, float> c[9];
#pragma unroll
    for (int j = 0; j < 9; j++) wmma::fill_fragment(c[j], 0.f);

    for (int kk = 0; kk < 128; kk += 16) {
        wmma::fragment<wmma::matrix_a, 16, 16, 16, __nv_bfloat16, wmma::row_major> ah, al;
        wmma::load_matrix_sync(ah, sAh + (w * 16) * LDA + kk, LDA);
        wmma::load_matrix_sync(al, sAl + (w * 16) * LDA + kk, LDA);
#pragma unroll
        for (int j = 0; j < 9; j++) {
            wmma::fragment<wmma::matrix_b, 16, 16, 16, __nv_bfloat16, wmma::row_major> bh, bl;
            wmma::load_matrix_sync(bh, g_w1h + kk * 144 + j * 16, 144);
            wmma::load_matrix_sync(bl, g_w1l + kk * 144 + j * 16, 144);
            wmma::mma_sync(c[j], ah, bh, c[j]);
            wmma::mma_sync(c[j], al, bh, c[j]);
            wmma::mma_sync(c[j], ah, bl, c[j]);
        }
    }
    __syncthreads();   // done with sA, reuse raw as stage
#pragma unroll
    for (int j = 0; j < 9; j++)
        wmma::store_matrix_sync(stage + (w * 16) * ST1 + j * 16, c[j], ST1, wmma::mem_row_major);
    __syncthreads();

    // epilogue: h1 -> fp16, alpha cols -> fp32
    {
        int r = tid >> 1, half = tid & 1;
        int row = row0 + r;
        if (row < NN) {
            const float* sp = stage + r * ST1 + half * 64;
            uint4* dp = (uint4*)(g_h1h + (size_t)row * 128 + half * 64);
#pragma unroll
            for (int q = 0; q < 8; q++) {
                float4 a = *(const float4*)(sp + 8 * q);
                float4 b = *(const float4*)(sp + 8 * q + 4);
                __half2 h0 = __floats2half2_rn(a.x, a.y);
                __half2 h1 = __floats2half2_rn(a.z, a.w);
                __half2 h2 = __floats2half2_rn(b.x, b.y);
                __half2 h3 = __floats2half2_rn(b.z, b.w);
                uint4 u;
                u.x = *(uint32_t*)&h0; u.y = *(uint32_t*)&h1;
                u.z = *(uint32_t*)&h2; u.w = *(uint32_t*)&h3;
                dp[q] = u;
            }
        }
    }
    if (tid < 128) {
        int row = row0 + tid;
        if (row < NN) {
            const float* sp = stage + tid * ST1 + 128;
#pragma unroll
            for (int h = 0; h < 4; h++) {
                g_as1[row * 4 + h] = sp[2 * h];
                g_ad1[row * 4 + h] = sp[2 * h + 1];
            }
        }
    }
}

// ---------------- GEMM2: [h2 | as2 | ad2] = relu(out1) @ [W2 | W2@P2] ---------
#define ST2 84
__global__ __launch_bounds__(256)
void k_gemm2_mma() {
    extern __shared__ char raw[];
    __nv_bfloat16* sAh = (__nv_bfloat16*)raw;
    __nv_bfloat16* sAl = sAh + 128 * LDA;
    float* stage = (float*)raw;
    int tid = threadIdx.x;
    int row0 = blockIdx.x * 128;

    for (int i = tid; i < 4096; i += 256) {
        int r = i >> 5, c4 = i & 31;
        float4 v = make_float4(0.f, 0.f, 0.f, 0.f);
        if (row0 + r < NN) v = ((const float4*)g_out1)[(size_t)(row0 + r) * 32 + c4];
        int base = r * LDA + c4 * 4;
        float vv[4] = {fmaxf(v.x, 0.f), fmaxf(v.y, 0.f), fmaxf(v.z, 0.f), fmaxf(v.w, 0.f)};
#pragma unroll
        for (int j = 0; j < 4; j++) {
            __nv_bfloat16 h = __float2bfloat16(vv[j]);
            sAh[base + j] = h;
            sAl[base + j] = __float2bfloat16(vv[j] - __bfloat162float(h));
        }
    }
    __syncthreads();

    int w = tid >> 5;
    wmma::fragment<wmma::accumulator, 16, 16, 16, float> c[5];
#pragma unroll
    for (int j = 0; j < 5; j++) wmma::fill_fragment(c[j], 0.f);

    for (int kk = 0; kk < 128; kk += 16) {
        wmma::fragment<wmma::matrix_a, 16, 16, 16, __nv_bfloat16, wmma::row_major> ah, al;
        wmma::load_matrix_sync(ah, sAh + (w * 16) * LDA + kk, LDA);
        wmma::load_matrix_sync(al, sAl + (w * 16) * LDA + kk, LDA);
#pragma unroll
        for (int j = 0; j < 5; j++) {
            wmma::fragment<wmma::matrix_b, 16, 16, 16, __nv_bfloat16, wmma::row_major> bh, bl;
            wmma::load_matrix_sync(bh, g_w2h + kk * 80 + j * 16, 80);
            wmma::load_matrix_sync(bl, g_w2l + kk * 80 + j * 16, 80);
            wmma::mma_sync(c[j], ah, bh, c[j]);
            wmma::mma_sync(c[j], al, bh, c[j]);
            wmma::mma_sync(c[j], ah, bl, c[j]);
        }
    }
    __syncthreads();
#pragma unroll
    for (int j = 0; j < 5; j++)
        wmma::store_matrix_sync(stage + (w * 16) * ST2 + j * 16, c[j], ST2, wmma::mem_row_major);
    __syncthreads();

    {
        int r = tid >> 1, half = tid & 1;
        int row = row0 + r;
        if (row < NN) {
            const float* sp = stage + r * ST2 + half * 32;
            uint4* dp = (uint4*)(g_h2h + (size_t)row * 64 + half * 32);
#pragma unroll
            for (int q = 0; q < 4; q++) {
                float4 a = *(const float4*)(sp + 8 * q);
                float4 b = *(const float4*)(sp + 8 * q + 4);
                __half2 h0 = __floats2half2_rn(a.x, a.y);
                __half2 h1 = __floats2half2_rn(a.z, a.w);
                __half2 h2 = __floats2half2_rn(b.x, b.y);
                __half2 h3 = __floats2half2_rn(b.z, b.w);
                uint4 u;
                u.x = *(uint32_t*)&h0; u.y = *(uint32_t*)&h1;
                u.z = *(uint32_t*)&h2; u.w = *(uint32_t*)&h3;
                dp[q] = u;
            }
        }
    }
    if (tid < 128) {
        int row = row0 + tid;
        if (row < NN) {
            g_as2[row] = stage[tid * ST2 + 64];
            g_ad2[row] = stage[tid * ST2 + 65];
        }
    }
}

// ---------------- CSR construction ------------------------------------------
__global__ void k_deginit() {
    int i = blockIdx.x * blockDim.x + threadIdx.x;
    if (i < NN) g_deg[i] = 1;
    if (i == 0) g_off[NN] = ET;
}

__global__ void k_hist(const int* __restrict__ ei) {
    int i = blockIdx.x * blockDim.x + threadIdx.x;
#pragma unroll
    for (int q = 0; q < 4; q++) {
        int e = i + q * 200000;
        if (i < 200000) atomicAdd(&g_deg[ei[NE + e]], 1);
    }
}

__global__ void k_scanA() {
    __shared__ int sh[256];
    int i = blockIdx.x * 256 + threadIdx.x;
    sh[threadIdx.x] = (i < NN) ? g_deg[i] : 0;
    __syncthreads();
#pragma unroll
    for (int o = 128; o >= 1; o >>= 1) {
        if (threadIdx.x < o) sh[threadIdx.x] += sh[threadIdx.x + o];
        __syncthreads();
    }
    if (threadIdx.x == 0) g_bsum[blockIdx.x] = sh[0];
}

__global__ void k_scanB() {
    __shared__ int sh[256];
    int t = threadIdx.x;
    int v = (t < NBLK) ? g_bsum[t] : 0;
    sh[t] = v;
    __syncthreads();
#pragma unroll
    for (int o = 1; o < 256; o <<= 1) {
        int tv = (t >= o) ? sh[t - o] : 0;
        __syncthreads();
        sh[t] += tv;
        __syncthreads();
    }
    if (t < NBLK) g_boff[t] = sh[t] - v;   // exclusive
}

__global__ void k_scanC() {
    __shared__ int sh[256];
    int t = threadIdx.x;
    int i = blockIdx.x * 256 + t;
    int v = (i < NN) ? g_deg[i] : 0;
    sh[t] = v;
    __syncthreads();
#pragma unroll
    for (int o = 1; o < 256; o <<= 1) {
        int tv = (t >= o) ? sh[t - o] : 0;
        __syncthreads();
        sh[t] += tv;
        __syncthreads();
    }
    if (i < NN) {
        int off = g_boff[blockIdx.x] + sh[t] - v;
        g_off[i] = off;
        g_cur[i] = off;
    }
}

__global__ void k_fill(const int* __restrict__ ei) {
    int i = blockIdx.x * blockDim.x + threadIdx.x;
    if (i >= 212500) return;
#pragma unroll
    for (int q = 0; q < 4; q++) {
        int e = i + q * 212500;
        int s, d;
        if (e < NE) { s = ei[e]; d = ei[NE + e]; }
        else        { s = e - NE; d = s; }
        int pos = atomicAdd(&g_cur[d], 1);
        g_srcidx[pos] = s;
    }
}

// ---------------- gather1: two-phase softmax aggregation (4 heads, fp16 h) ---
__global__ __launch_bounds__(256)
void k_gather1(const float* __restrict__ b1) {
    int n = blockIdx.x * 8 + (threadIdx.x >> 5);
    if (n >= NN) return;
    int lane = threadIdx.x & 31, h = lane >> 3;
    float adh = g_ad1[4 * n + h];
    int beg = g_off[n], end = g_off[n + 1];

    // phase 1: per-head max of as over neighbors (lanes parallel over edges)
    float4 mx = make_float4(-3.4e38f, -3.4e38f, -3.4e38f, -3.4e38f);
    for (int j = beg + lane; j < end; j += 32) {
        int s = g_srcidx[j];
        float4 a = *(const float4*)(g_as1 + 4 * s);
        mx.x = fmaxf(mx.x, a.x); mx.y = fmaxf(mx.y, a.y);
        mx.z = fmaxf(mx.z, a.z); mx.w = fmaxf(mx.w, a.w);
    }
#pragma unroll
    for (int o = 16; o >= 1; o >>= 1) {
        mx.x = fmaxf(mx.x, __shfl_xor_sync(0xffffffffu, mx.x, o));
        mx.y = fmaxf(mx.y, __shfl_xor_sync(0xffffffffu, mx.y, o));
        mx.z = fmaxf(mx.z, __shfl_xor_sync(0xffffffffu, mx.z, o));
        mx.w = fmaxf(mx.w, __shfl_xor_sync(0xffffffffu, mx.w, o));
    }
    float mh = (h == 0) ? mx.x : (h == 1) ? mx.y : (h == 2) ? mx.z : mx.w;
    mh = lrelu(mh + adh);   // lrelu monotonic: max of lrelu = lrelu of max

    // phase 2: independent-iteration weighted accumulation
    float4 acc = make_float4(0.f, 0.f, 0.f, 0.f);
    float den = 0.f;
    int s0 = 0; float a0 = 0.f; uint2 u0 = make_uint2(0, 0);
    if (beg < end) {
        s0 = g_srcidx[beg];
        a0 = g_as1[4 * s0 + h];
        u0 = *(const uint2*)(g_h1h + (size_t)s0 * 128 + 4 * lane);
    }
    for (int j = beg; j < end; j++) {
        int s1 = 0; float a1 = 0.f; uint2 u1 = make_uint2(0, 0);
        if (j + 1 < end) {
            s1 = g_srcidx[j + 1];
            a1 = g_as1[4 * s1 + h];
            u1 = *(const uint2*)(g_h1h + (size_t)s1 * 128 + 4 * lane);
        }
        float w = __expf(lrelu(a0 + adh) - mh);
        den += w;
        float2 f0 = __half22float2(*(__half2*)&u0.x);
        float2 f1 = __half22float2(*(__half2*)&u0.y);
        acc.x += w * f0.x; acc.y += w * f0.y;
        acc.z += w * f1.x; acc.w += w * f1.y;
        s0 = s1; a0 = a1; u0 = u1;
    }
    float inv = 1.f / (den + 1e-16f);
    float4 bv = *(const float4*)(b1 + 4 * lane);
    *(float4*)(g_out1 + (size_t)n * 128 + 4 * lane) =
        make_float4(acc.x * inv + bv.x, acc.y * inv + bv.y,
                    acc.z * inv + bv.z, acc.w * inv + bv.w);
}

// ---------------- gather2: two-phase (1 head, fp16 h) -------------------------
__global__ __launch_bounds__(256)
void k_gather2(const float* __restrict__ b2, float* __restrict__ out) {
    int n = blockIdx.x * 8 + (threadIdx.x >> 5);
    if (n >= NN) return;
    int lane = threadIdx.x & 31;
    float adh = g_ad2[n];
    int beg = g_off[n], end = g_off[n + 1];

    float mx = -3.4e38f;
    for (int j = beg + lane; j < end; j += 32)
        mx = fmaxf(mx, g_as2[g_srcidx[j]]);
#pragma unroll
    for (int o = 16; o >= 1; o >>= 1)
        mx = fmaxf(mx, __shfl_xor_sync(0xffffffffu, mx, o));
    float mh = lrelu(mx + adh);

    float2 acc = make_float2(0.f, 0.f);
    float den = 0.f;
    int s0 = 0; float a0 = 0.f; uint32_t u0 = 0;
    if (beg < end) {
        s0 = g_srcidx[beg];
        a0 = g_as2[s0];
        u0 = *(const uint32_t*)(g_h2h + (size_t)s0 * 64 + 2 * lane);
    }
    for (int j = beg; j < end; j++) {
        int s1 = 0; float a1 = 0.f; uint32_t u1 = 0;
        if (j + 1 < end) {
            s1 = g_srcidx[j + 1];
            a1 = g_as2[s1];
            u1 = *(const uint32_t*)(g_h2h + (size_t)s1 * 64 + 2 * lane);
        }
        float w = __expf(lrelu(a0 + adh) - mh);
        den += w;
        float2 f = __half22float2(*(__half2*)&u0);
        acc.x += w * f.x; acc.y += w * f.y;
        s0 = s1; a0 = a1; u0 = u1;
    }
    float inv = 1.f / (den + 1e-16f);
    float2 bv = *(const float2*)(b2 + 2 * lane);
    *(float2*)(out + (size_t)n * 64 + 2 * lane) =
        make_float2(acc.x * inv + bv.x, acc.y * inv + bv.y);
}

// ---------------- launch ------------------------------------------------------
extern "C" void kernel_launch(void* const* d_in, const int* in_sizes, int n_in,
                              void* d_out, int out_size) {
    const float* x   = (const float*)d_in[0];
    const int*   ei  = (const int*)d_in[1];
    const float* W1  = (const float*)d_in[2];
    const float* as1 = (const float*)d_in[3];
    const float* ad1 = (const float*)d_in[4];
    const float* b1  = (const float*)d_in[5];
    const float* W2  = (const float*)d_in[6];
    const float* as2 = (const float*)d_in[7];
    const float* ad2 = (const float*)d_in[8];
    const float* b2  = (const float*)d_in[9];
    float* out = (float*)d_out;

    static bool attr_done = false;
    const int smem1 = 128 * ST1 * 4;     // 75776
    const int smem2 = 128 * LDA * 2 * 2; // 69632
    if (!attr_done) {
        cudaFuncSetAttribute(k_gemm1_mma, cudaFuncAttributeMaxDynamicSharedMemorySize, smem1);
        cudaFuncSetAttribute(k_gemm2_mma, cudaFuncAttributeMaxDynamicSharedMemorySize, smem2);
        attr_done = true;
    }

    // CSR build
    k_deginit<<<NBLK, 256>>>();
    k_hist<<<(200000 + 255) / 256, 256>>>(ei);
    k_scanA<<<NBLK, 256>>>();
    k_scanB<<<1, 256>>>();
    k_scanC<<<NBLK, 256>>>();
    k_fill<<<(212500 + 255) / 256, 256>>>(ei);

    // weights -> bf16 split with fused alpha columns
    k_convw<<<112, 256>>>(W1, W2, as1, ad1, as2, ad2);

    // layer 1
    k_gemm1_mma<<<NP / 128, 256, smem1>>>(x);
    k_gather1<<<(NN + 7) / 8, 256>>>(b1);

    // layer 2
    k_gemm2_mma<<<NP / 128, 256, smem2>>>();
    k_gather2<<<(NN + 7) / 8, 256>>>(b2, out);
}